// round 2
// baseline (speedup 1.0000x reference)
#include <cuda_runtime.h>

// IoU distance: out[i][j] = inter/union + 1e-16
//   inter = min(lw_i, rw_j) * min(lh_i, rh_j)
//   union = lw_i*lh_i + rw_j*rh_j - inter
//
// lhs: [N,2] fp32 (N = 100000), rhs: [512,2] fp32, out: [N,512] fp32.
//
// Layout: 128 threads/block; thread t owns columns j = 4t..4t+3 (full row of
// 512 per block iteration). rhs pairs live in registers for the whole row
// loop; each row costs one broadcast LDG.64 of (lw,lh) and one STG.128 per
// thread. Division via MUFU.RCP (__fdividef) -- rel err ~1e-7 << 1e-3.

#ifndef EPS_IOU
#define EPS_IOU 1e-16f
#endif

__global__ __launch_bounds__(128, 16)
void iou_distance_kernel(const float2* __restrict__ lhs,
                         const float4* __restrict__ rhs4,   // rhs viewed as float4 (2 boxes per load)
                         float4* __restrict__ out4,         // out viewed as float4
                         int n_rows)
{
    const int t = threadIdx.x;           // 0..127 -> columns 4t..4t+3

    // Load this thread's 4 rhs boxes once; precompute areas.
    float rw[4], rh[4], ra[4];
    {
        float4 p0 = rhs4[2 * t + 0];     // boxes 4t, 4t+1
        float4 p1 = rhs4[2 * t + 1];     // boxes 4t+2, 4t+3
        rw[0] = p0.x; rh[0] = p0.y;
        rw[1] = p0.z; rh[1] = p0.w;
        rw[2] = p1.x; rh[2] = p1.y;
        rw[3] = p1.z; rh[3] = p1.w;
#pragma unroll
        for (int k = 0; k < 4; ++k) ra[k] = rw[k] * rh[k];
    }

    for (int i = blockIdx.x; i < n_rows; i += gridDim.x) {
        const float2 l = lhs[i];                 // broadcast load (same addr per block)
        const float lw = l.x, lh = l.y;
        const float la = lw * lh;

        float o[4];
#pragma unroll
        for (int k = 0; k < 4; ++k) {
            const float iw    = fminf(lw, rw[k]);
            const float ih    = fminf(lh, rh[k]);
            const float inter = iw * ih;
            const float uni   = la + ra[k] - inter;
            o[k] = __fdividef(inter, uni) + EPS_IOU;
        }

        float4 v;
        v.x = o[0]; v.y = o[1]; v.z = o[2]; v.w = o[3];
        out4[(long long)i * 128 + t] = v;
    }
}

extern "C" void kernel_launch(void* const* d_in, const int* in_sizes, int n_in,
                              void* d_out, int out_size)
{
    const float2* lhs  = (const float2*)d_in[0];
    const float4* rhs4 = (const float4*)d_in[1];
    float4*       out4 = (float4*)d_out;

    const int n_rows = in_sizes[0] / 2;          // 100000

    int grid = n_rows < 2048 ? (n_rows > 0 ? n_rows : 1) : 2048;

    iou_distance_kernel<<<grid, 128>>>(lhs, rhs4, out4, n_rows);
}

// round 3
// speedup vs baseline: 1.3785x; 1.3785x over previous
#include <cuda_runtime.h>

// IoU distance: out[i][j] = inter/union + 1e-16
//   inter = min(lw_i, rw_j) * min(lh_i, rh_j)
//   union = lw_i*lh_i + rw_j*rh_j - inter
//
// lhs: [N,2] fp32 (N = 100000), rhs: [512,2] fp32, out: [N,512] fp32.
//
// R2: 4 rows per iteration (4 independent dependency chains per thread),
// contiguous per-block row chunks for store locality, streaming stores
// (__stcs) since the 205MB output exceeds L2. rhs stays in registers.

#ifndef EPS_IOU
#define EPS_IOU 1e-16f
#endif

#define ROWS_PER_IT 4

__global__ __launch_bounds__(128, 8)
void iou_distance_kernel(const float2* __restrict__ lhs,
                         const float4* __restrict__ rhs4,
                         float4* __restrict__ out4,
                         int row_begin_stride,   // chunk size per block (multiple of 4)
                         int n_rows)
{
    const int t = threadIdx.x;               // 0..127 -> columns 4t..4t+3

    // This thread's 4 rhs boxes, held in registers for the whole kernel.
    float rw[4], rh[4], ra[4];
    {
        float4 p0 = rhs4[2 * t + 0];
        float4 p1 = rhs4[2 * t + 1];
        rw[0] = p0.x; rh[0] = p0.y;
        rw[1] = p0.z; rh[1] = p0.w;
        rw[2] = p1.x; rh[2] = p1.y;
        rw[3] = p1.z; rh[3] = p1.w;
#pragma unroll
        for (int k = 0; k < 4; ++k) ra[k] = rw[k] * rh[k];
    }

    int row0    = blockIdx.x * row_begin_stride;
    int row_end = row0 + row_begin_stride;
    if (row_end > n_rows) row_end = n_rows;

    const float2* lp = lhs + row0;
    float4*       op = out4 + (long long)row0 * 128 + t;

    for (int i = row0; i < row_end; i += ROWS_PER_IT) {
        // Load 4 rows' (w,h) up front -> 4 independent chains.
        float2 l[ROWS_PER_IT];
#pragma unroll
        for (int r = 0; r < ROWS_PER_IT; ++r) l[r] = lp[r];
        lp += ROWS_PER_IT;

#pragma unroll
        for (int r = 0; r < ROWS_PER_IT; ++r) {
            const float lw = l[r].x, lh = l[r].y;
            const float la = lw * lh;

            float o[4];
#pragma unroll
            for (int k = 0; k < 4; ++k) {
                const float iw    = fminf(lw, rw[k]);
                const float ih    = fminf(lh, rh[k]);
                const float inter = iw * ih;
                const float uni   = la + ra[k] - inter;
                o[k] = __fdividef(inter, uni) + EPS_IOU;
            }

            float4 v;
            v.x = o[0]; v.y = o[1]; v.z = o[2]; v.w = o[3];
            __stcs(op + (long long)r * 128, v);   // streaming store: output >> L2
        }
        op += (long long)ROWS_PER_IT * 128;
    }
}

extern "C" void kernel_launch(void* const* d_in, const int* in_sizes, int n_in,
                              void* d_out, int out_size)
{
    const float2* lhs  = (const float2*)d_in[0];
    const float4* rhs4 = (const float4*)d_in[1];
    float4*       out4 = (float4*)d_out;

    const int n_rows = in_sizes[0] / 2;      // 100000

    // Contiguous chunks, multiple of ROWS_PER_IT. 100000 -> 1000 blocks x 100 rows.
    int chunk = 100;
    int grid  = (n_rows + chunk - 1) / chunk;

    iou_distance_kernel<<<grid, 128>>>(lhs, rhs4, out4, chunk, n_rows);
}

// round 4
// speedup vs baseline: 1.4587x; 1.0582x over previous
#include <cuda_runtime.h>

// IoU distance: out[i][j] = inter/union + 1e-16
//   inter = min(lw_i, rw_j) * min(lh_i, rh_j)
//   union = lw_i*lh_i + rw_j*rh_j - inter
//
// lhs: [N,2] fp32 (N = 100000), rhs: [512,2] fp32, out: [N,512] fp32.
//
// R4: smaller chunks (64 rows -> 1563 blocks) to lift grid-limited occupancy;
// division as raw MUFU.RCP + single FFMA folding the +EPS; 4-row ILP and
// streaming STG.128 kept from R3.

#ifndef EPS_IOU
#define EPS_IOU 1e-16f
#endif

#define ROWS_PER_IT 4

__device__ __forceinline__ float rcp_approx(float x) {
    float r;
    asm("rcp.approx.ftz.f32 %0, %1;" : "=f"(r) : "f"(x));
    return r;
}

__global__ __launch_bounds__(128, 8)
void iou_distance_kernel(const float2* __restrict__ lhs,
                         const float4* __restrict__ rhs4,
                         float4* __restrict__ out4,
                         int chunk,              // rows per block (multiple of 4)
                         int n_rows)
{
    const int t = threadIdx.x;               // 0..127 -> columns 4t..4t+3

    // This thread's 4 rhs boxes, register-resident for the whole kernel.
    float rw[4], rh[4], ra[4];
    {
        float4 p0 = rhs4[2 * t + 0];
        float4 p1 = rhs4[2 * t + 1];
        rw[0] = p0.x; rh[0] = p0.y;
        rw[1] = p0.z; rh[1] = p0.w;
        rw[2] = p1.x; rh[2] = p1.y;
        rw[3] = p1.z; rh[3] = p1.w;
#pragma unroll
        for (int k = 0; k < 4; ++k) ra[k] = rw[k] * rh[k];
    }

    int row0    = blockIdx.x * chunk;
    if (row0 >= n_rows) return;
    int row_end = row0 + chunk;
    if (row_end > n_rows) row_end = n_rows;

    const float2* lp = lhs + row0;
    float4*       op = out4 + (long long)row0 * 128 + t;

    for (int i = row0; i < row_end; i += ROWS_PER_IT) {
        // 4 rows' (w,h) up front -> 4 independent chains.
        float2 l[ROWS_PER_IT];
#pragma unroll
        for (int r = 0; r < ROWS_PER_IT; ++r) l[r] = lp[r];
        lp += ROWS_PER_IT;

#pragma unroll
        for (int r = 0; r < ROWS_PER_IT; ++r) {
            const float lw = l[r].x, lh = l[r].y;
            const float la = lw * lh;

            float o[4];
#pragma unroll
            for (int k = 0; k < 4; ++k) {
                const float iw    = fminf(lw, rw[k]);
                const float ih    = fminf(lh, rh[k]);
                const float inter = iw * ih;                  // FMUL
                const float uni   = (la + ra[k]) - inter;     // FADD, FADD
                o[k] = fmaf(inter, rcp_approx(uni), EPS_IOU); // MUFU + FFMA
            }

            float4 v;
            v.x = o[0]; v.y = o[1]; v.z = o[2]; v.w = o[3];
            __stcs(op + (long long)r * 128, v);   // streaming store: output >> L2
        }
        op += (long long)ROWS_PER_IT * 128;
    }
}

extern "C" void kernel_launch(void* const* d_in, const int* in_sizes, int n_in,
                              void* d_out, int out_size)
{
    const float2* lhs  = (const float2*)d_in[0];
    const float4* rhs4 = (const float4*)d_in[1];
    float4*       out4 = (float4*)d_out;

    const int n_rows = in_sizes[0] / 2;      // 100000

    // 64-row contiguous chunks -> 1563 blocks; tail chunk = 32 rows (still %4).
    int chunk = 64;
    int grid  = (n_rows + chunk - 1) / chunk;

    iou_distance_kernel<<<grid, 128>>>(lhs, rhs4, out4, chunk, n_rows);
}